// round 15
// baseline (speedup 1.0000x reference)
#include <cuda_runtime.h>
#include <cuda_fp16.h>
#include <math.h>
#include <stdint.h>

#define BB 4
#define SS 1024
#define DD 256
#define HH 512
#define NTY 20
#define NSMP 50
#define MM (BB*SS)          /* 4096 (b,s) rows */
#define RTOT (MM*NSMP)      /* 204800 GEMM rows */

typedef unsigned long long ull;
typedef unsigned int uint32;

/* ---------------- scratch (device globals; no allocs allowed) -------------- */
__device__ __align__(16) float g_hvec[MM*HH];   /* [b,s, pe|temb]   8MB */
__device__ __align__(16) float g_hid [MM*HH];   /* aggregated / post-LN 8MB */
__device__ __align__(16) float g_y   [MM*HH];   /* hln @ w_in^T     8MB */
/* fp16 weights, k-chunk-major: elem (n,k) at (k/16)*8192 + n*16 + (k%16) */
__device__ __align__(16) __half g_wh [HH*HH];   /* w_noise fp16 */
__device__ __align__(16) __half g_wih[HH*HH];   /* w_in hi */
__device__ __align__(16) __half g_wil[HH*HH];   /* w_in lo */
__device__ __align__(16) float g_part[2*RTOT];  /* partial relu-dots 1.6MB */
__device__ float g_asv[MM], g_bsv[MM], g_agv[MM], g_bgv[MM];

/* ---------------- small helpers ---------------- */
__device__ __forceinline__ ull ffma2(ull a, ull b, ull c){
  ull d; asm("fma.rn.f32x2 %0, %1, %2, %3;" : "=l"(d) : "l"(a), "l"(b), "l"(c)); return d;
}
union F2 { ull u; float2 f; };
__device__ __forceinline__ ull pack2(float x, float y){ F2 t; t.f = make_float2(x,y); return t.u; }

__device__ __forceinline__ float block_sum256(float v){
  __shared__ float sh[8];
  int lane = threadIdx.x & 31, w = threadIdx.x >> 5;
  #pragma unroll
  for(int o=16;o;o>>=1) v += __shfl_xor_sync(0xffffffffu, v, o);
  if(lane==0) sh[w] = v;
  __syncthreads();
  if(w==0){
    float r = (lane<8)?sh[lane]:0.f;
    #pragma unroll
    for(int o=4;o;o>>=1) r += __shfl_xor_sync(0xffffffffu, r, o);
    if(lane==0) sh[0]=r;
  }
  __syncthreads();
  float r = sh[0];
  __syncthreads();
  return r;
}

__device__ __forceinline__ float softplusf(float x){
  return fmaxf(x,0.f) + log1pf(expf(-fabsf(x)));
}

__device__ __forceinline__ uint32 smem_u32(const void* p){
  uint32 a; asm("{ .reg .u64 t; cvta.to.shared.u64 t, %1; cvt.u32.u64 %0, t; }" : "=r"(a) : "l"(p));
  return a;
}

/* ---------------- sm80-class tensor core primitives (portable) ------------- */
#define LDSM4(rg, addr) \
  asm volatile("ldmatrix.sync.aligned.m8n8.x4.shared.b16 {%0,%1,%2,%3}, [%4];" \
    : "=r"((rg)[0]),"=r"((rg)[1]),"=r"((rg)[2]),"=r"((rg)[3]) : "r"(addr))

#define MMA16816(cd, a, b0, b1) \
  asm volatile("mma.sync.aligned.m16n8k16.row.col.f32.f16.f16.f32 " \
    "{%0,%1,%2,%3},{%4,%5,%6,%7},{%8,%9},{%0,%1,%2,%3};" \
    : "+f"((cd)[0]),"+f"((cd)[1]),"+f"((cd)[2]),"+f"((cd)[3]) \
    : "r"((a)[0]),"r"((a)[1]),"r"((a)[2]),"r"((a)[3]), "r"(b0),"r"(b1))

#define CPA16(s,g)  asm volatile("cp.async.cg.shared.global [%0], [%1], 16;" :: "r"(s), "l"(g))
#define CPCOMMIT()  asm volatile("cp.async.commit_group;" ::: "memory")
#define CPWAIT(n)   asm volatile("cp.async.wait_group %0;" :: "n"(n) : "memory")

/* -------- k1: pe + type emb + per-event projections; blocks 0..127 also
   convert w_noise -> fp16 and w_in -> fp16 hi/lo (folded former k0) -------- */
__global__ void k1_pre(const int* __restrict__ etype, const float* __restrict__ etime,
                       const float* __restrict__ wt, const float* __restrict__ table,
                       const float* __restrict__ wsig, const float* __restrict__ wgate,
                       const float* __restrict__ wn, const float* __restrict__ wi){
  int bs = blockIdx.x; int t = threadIdx.x;
  if(bs < 128){                                /* folded k0: weight conversion */
    int g = bs*256 + t;                        /* 32768 threads, 8 elems each */
    int n = g >> 6; int k = (g & 63) * 8;
    int dst = (k>>4)*8192 + n*16 + (k&15);
    {
      const float4* s = reinterpret_cast<const float4*>(wn + (size_t)n*HH + k);
      float4 v0 = s[0], v1 = s[1];
      float xs[8] = {v0.x,v0.y,v0.z,v0.w,v1.x,v1.y,v1.z,v1.w};
      union { __half b[8]; uint4 u; } h;
      #pragma unroll
      for(int e=0;e<8;e++) h.b[e] = __float2half_rn(xs[e]);
      *reinterpret_cast<uint4*>(g_wh + dst) = h.u;
    }
    {
      const float4* s = reinterpret_cast<const float4*>(wi + (size_t)n*HH + k);
      float4 v0 = s[0], v1 = s[1];
      float xs[8] = {v0.x,v0.y,v0.z,v0.w,v1.x,v1.y,v1.z,v1.w};
      union { __half b[8]; uint4 u; } hi, lo;
      #pragma unroll
      for(int e=0;e<8;e++){
        __half h = __float2half_rn(xs[e]);
        hi.b[e] = h;
        lo.b[e] = __float2half_rn(xs[e] - __half2float(h));
      }
      *reinterpret_cast<uint4*>(g_wih + dst) = hi.u;
      *reinterpret_cast<uint4*>(g_wil + dst) = lo.u;
    }
  }
  int s = bs & (SS-1);
  float tv = table[(size_t)etype[bs]*DD + t];
  float tm = etime[bs];
  if(t < DD/2){
    double div = exp(-(double)(2*t) * (9.210340371976184/256.0)); /* ln(1e4)/d */
    float arg = (float)((double)s * div) + tm * wt[t];
    g_hvec[(size_t)bs*HH + t]        = sinf(arg);
    g_hvec[(size_t)bs*HH + DD/2 + t] = cosf(arg);
  }
  g_hvec[(size_t)bs*HH + DD + t] = tv;
  float r;
  r = block_sum256(tv * wsig[t]);      if(t==0) g_asv[bs]=r;
  r = block_sum256(tv * wsig[DD+t]);   if(t==0) g_bsv[bs]=r;
  r = block_sum256(tv * wgate[t]);     if(t==0) g_agv[bs]=r;
  r = block_sum256(tv * wgate[DD+t]);  if(t==0) g_bgv[bs]=r;
}

/* -------- k2: causal gated score aggregation, TI=32 rows per block ---------
   64KB dynamic smem for the score tile; biggest i-tiles launch first.      */
#define K2_SMEM (32*256*8)
__global__ void __launch_bounds__(256) k2_agg(const float* __restrict__ etime){
  extern __shared__ ull s_w[];                 /* [32][256] = 64KB */
  __shared__ float s_bs[32], s_bg[32], s_ti[32];
  int bx = blockIdx.x; int b = bx >> 5;
  int i0 = (31 - (bx & 31)) << 5;             /* reversed: big blocks first */
  int t = threadIdx.x;
  if(t < 32){
    int i = b*SS + i0 + t;
    s_bs[t] = g_bsv[i]; s_bg[t] = g_bgv[i]; s_ti[t] = etime[i];
  }
  __syncthreads();
  ull acc[32];
  #pragma unroll
  for(int r=0;r<32;r++) acc[r]=0ull;
  int jend = i0 + 31;
  for(int j0=0;j0<jend;j0+=256){
    int j = j0 + t;
    float aj_s = g_asv[b*SS+j], aj_g = g_agv[b*SS+j], tj = etime[b*SS+j];
    #pragma unroll
    for(int r=0;r<32;r++){
      float sig  = __logf(1.f + __expf(aj_s + s_bs[r]));
      float gate = 1.f/(1.f + __expf(-(aj_g + s_bg[r])));
      float td   = fabsf(s_ti[r]-tj);
      float wv   = (j < i0+r) ? gate*__expf(-sig*td) : 0.f;
      s_w[r*256 + t] = pack2(wv, wv);
    }
    __syncthreads();
    int jcnt = min(256, jend - j0);
    const ull* hv = reinterpret_cast<const ull*>(g_hvec) + ((size_t)(b*SS + j0))*256 + t;
    #pragma unroll 2
    for(int jj=0;jj<jcnt;jj++){
      ull v = hv[(size_t)jj*256];
      #pragma unroll
      for(int r=0;r<32;r++) acc[r] = ffma2(s_w[r*256 + jj], v, acc[r]);
    }
    __syncthreads();
  }
  #pragma unroll
  for(int r=0;r<32;r++)
    reinterpret_cast<ull*>(g_hid)[((size_t)(b*SS + i0 + r))*256 + t] = acc[r];
}

/* -------- k3: LayerNorm (in-place) + mark_probs softmax -------------------- */
__global__ void k3_ln(const float* __restrict__ gamma, const float* __restrict__ beta,
                      const float* __restrict__ wpred, float* __restrict__ marks){
  __shared__ float s_n[HH];
  __shared__ float slog[NTY];
  int bs = blockIdx.x, t = threadIdx.x;
  float2 h = reinterpret_cast<const float2*>(g_hid)[(size_t)bs*256 + t];
  float mean = block_sum256(h.x + h.y) * (1.f/HH);
  float dx = h.x - mean, dy = h.y - mean;
  float var = block_sum256(dx*dx + dy*dy) * (1.f/HH);
  float inv = rsqrtf(var + 1e-6f);
  float n0 = dx*inv*gamma[2*t]   + beta[2*t];
  float n1 = dy*inv*gamma[2*t+1] + beta[2*t+1];
  reinterpret_cast<float2*>(g_hid)[(size_t)bs*256 + t] = make_float2(n0,n1);
  s_n[2*t]=n0; s_n[2*t+1]=n1;
  __syncthreads();
  int lane = t & 31, w = t >> 5;
  for(int nt = w; nt < NTY; nt += 8){
    float p = 0.f;
    for(int k=lane;k<HH;k+=32) p += s_n[k]*wpred[(size_t)nt*HH+k];
    #pragma unroll
    for(int o=16;o;o>>=1) p += __shfl_xor_sync(0xffffffffu,p,o);
    if(lane==0) slog[nt]=p;
  }
  __syncthreads();
  if(t==0){
    float mx=-1e30f;
    for(int c=0;c<NTY;c++) mx = fmaxf(mx, slog[c]);
    float e[NTY], sum=0.f;
    for(int c=0;c<NTY;c++){ e[c]=expf(slog[c]-mx); sum+=e[c]; }
    float is = 1.f/sum;
    for(int c=0;c<NTY;c++) marks[(size_t)bs*NTY + c] = e[c]*is;
  }
}

/* -------- k3y: y = hln @ w_in^T on tensor cores, 3-pass split-fp16 --------- */
#define Y_SAH(buf) ((buf)*3072)                 /* 64 rows x 48B pitch */
#define Y_SAL(buf) (6144 + (buf)*3072)
#define Y_SBH(buf) (12288 + (buf)*8192)         /* 256 n x 32B */
#define Y_SBL(buf) (28672 + (buf)*8192)
#define Y_SMEM 45056

__global__ void __launch_bounds__(256,1)
k3y_mma(){
  extern __shared__ char sm[];
  const uint32 sb = smem_u32(sm);
  const int t = threadIdx.x;
  const int lane = t & 31, w = t >> 5;
  const int wm = w & 1, wn = w >> 1;          /* 2 M-warps x 4 N-warps */
  const size_t m0 = (size_t)blockIdx.x * 64;
  const int n0 = blockIdx.y * 256;

  const int arow = t >> 1, ahalf = t & 1;     /* t<128 active for A */
  const float* aptr = g_hid + (m0 + arow)*HH + ahalf*8;

  auto loadB = [&](int kc, int buf){
    const char* srch = reinterpret_cast<const char*>(g_wih) + (size_t)kc*16384;
    const char* srcl = reinterpret_cast<const char*>(g_wil) + (size_t)kc*16384;
    #pragma unroll
    for(int j=0;j<2;j++){
      int i = t + j*256;
      int n = i >> 1, kq = i & 1;
      int soff = n*32 + ((kq ^ ((n>>2)&1)) << 4);
      int goff = (n0 + n)*32 + (kq << 4);
      CPA16(sb + Y_SBH(buf) + soff, srch + goff);
      CPA16(sb + Y_SBL(buf) + soff, srcl + goff);
    }
  };
  auto cvtstA = [&](int buf, float4 v0, float4 v1){
    if(t < 128){
      float xv[8] = {v0.x,v0.y,v0.z,v0.w,v1.x,v1.y,v1.z,v1.w};
      union { __half b[8]; uint4 u; } hi, lo;
      #pragma unroll
      for(int e=0;e<8;e++){
        __half h = __float2half_rn(xv[e]);
        hi.b[e] = h;
        lo.b[e] = __float2half_rn(xv[e] - __half2float(h));
      }
      int off = arow*48 + ahalf*16;
      *reinterpret_cast<uint4*>(sm + Y_SAH(buf) + off) = hi.u;
      *reinterpret_cast<uint4*>(sm + Y_SAL(buf) + off) = lo.u;
    }
  };

  float4 pv0, pv1;
  if(t < 128){ pv0 = *reinterpret_cast<const float4*>(aptr);
               pv1 = *reinterpret_cast<const float4*>(aptr + 4); }
  cvtstA(0, pv0, pv1);
  loadB(0, 0); CPCOMMIT();

  const uint32 a_off = (uint32)((wm*32 + (lane&15))*48 + (lane>>4)*16);
  const int bnl = (lane&7) + ((lane>>4)&1)*8;
  const uint32 b_off = (uint32)((wn*64 + bnl)*32
                     + ((((lane>>3)&1) ^ ((bnl>>2)&1)) << 4));

  float acc[2][8][4];
  #pragma unroll
  for(int mt=0;mt<2;mt++)
    #pragma unroll
    for(int nt=0;nt<8;nt++)
      #pragma unroll
      for(int c=0;c<4;c++) acc[mt][nt][c] = 0.f;

  for(int kc=0; kc<32; kc++){
    const int buf = kc & 1;
    if(kc < 31){
      if(t < 128){ pv0 = *reinterpret_cast<const float4*>(aptr + (kc+1)*16);
                   pv1 = *reinterpret_cast<const float4*>(aptr + (kc+1)*16 + 4); }
      loadB(kc+1, buf^1); CPCOMMIT();
      CPWAIT(1);
    } else CPWAIT(0);
    __syncthreads();

    uint32 af[2][4], al[2][4], bh[4][4], bl[4][4];
    const uint32 ahi = sb + Y_SAH(buf) + a_off;
    const uint32 alo = sb + Y_SAL(buf) + a_off;
    const uint32 bhb = sb + Y_SBH(buf) + b_off;
    const uint32 blb = sb + Y_SBL(buf) + b_off;

    LDSM4(af[0], ahi);  LDSM4(af[1], ahi + 16*48);
    LDSM4(al[0], alo);  LDSM4(al[1], alo + 16*48);
    #pragma unroll
    for(int x=0;x<4;x++){ LDSM4(bh[x], bhb + x*512); LDSM4(bl[x], blb + x*512); }

    #pragma unroll
    for(int mt=0;mt<2;mt++)
      #pragma unroll
      for(int x=0;x<4;x++){
        MMA16816(acc[mt][2*x],   af[mt], bh[x][0], bh[x][1]);
        MMA16816(acc[mt][2*x+1], af[mt], bh[x][2], bh[x][3]);
        MMA16816(acc[mt][2*x],   al[mt], bh[x][0], bh[x][1]);
        MMA16816(acc[mt][2*x+1], al[mt], bh[x][2], bh[x][3]);
        MMA16816(acc[mt][2*x],   af[mt], bl[x][0], bl[x][1]);
        MMA16816(acc[mt][2*x+1], af[mt], bl[x][2], bl[x][3]);
      }
    if(kc < 31) cvtstA(buf^1, pv0, pv1);
    __syncthreads();
  }

  /* write y (fp32) */
  const int r = lane >> 2, q = lane & 3;
  #pragma unroll
  for(int mt=0;mt<2;mt++){
    size_t row0 = m0 + wm*32 + mt*16 + r;
    size_t row1 = row0 + 8;
    #pragma unroll
    for(int nt=0;nt<8;nt++){
      int col = n0 + wn*64 + nt*8 + q*2;
      float* c = acc[mt][nt];
      *reinterpret_cast<float2*>(&g_y[row0*HH + col]) = make_float2(c[0],c[1]);
      *reinterpret_cast<float2*>(&g_y[row1*HH + col]) = make_float2(c[2],c[3]);
    }
  }
}

/* -------- k4: single-pass fp16 mma.sync GEMM, M=128 x N=256 per CTA --------
   512 threads / 16 warps (4 per SMSP); warp tile 32x64; K-chunk 32 with two
   16-k sub-steps; 3-stage cp.async ring; one __syncthreads per iteration.
   Group ledger: at top of iter kc pending groups = {kc, kc+1} -> CPWAIT(1)
   completes chunk kc while kc+1 stays in flight.                           */
#define K4_ST(st)      ((st)*28672)
#define K4_SA(st,sub)  (K4_ST(st) + (sub)*6144)          /* 128 rows x 48B */
#define K4_SB(st,sub)  (K4_ST(st) + 12288 + (sub)*8192)  /* 256 n x 32B */
#define K4_SMEM (3*28672)

__global__ void __launch_bounds__(512,1)
k4_mma(const float* __restrict__ noise, const float* __restrict__ wtime){
  extern __shared__ char sm[];
  const uint32 sb = smem_u32(sm);
  const int t = threadIdx.x;
  const int lane = t & 31, w = t >> 5;
  const int wm = w & 3, wn = w >> 2;          /* 4 M-warps x 4 N-warps */
  const size_t m0 = (size_t)blockIdx.x * 128;
  const int n0 = blockIdx.y * 256;

  const int arow = t >> 2, aq = t & 3;        /* 4 threads/row, 8 floats each */
  const float* aptr = noise + (m0 + arow)*HH + aq*8;

  auto loadB = [&](int kc2, int st){          /* kc2: 32-wide chunk index */
    #pragma unroll
    for(int sub=0; sub<2; sub++){
      const char* src = reinterpret_cast<const char*>(g_wh)
                      + (size_t)(kc2*2+sub)*16384;
      int n = t >> 1, kq = t & 1;             /* 512 lines of 16B */
      int soff = n*32 + ((kq ^ ((n>>2)&1)) << 4);
      int goff = (n0 + n)*32 + (kq << 4);
      CPA16(sb + K4_SB(st,sub) + soff, src + goff);
    }
  };
  auto cvtstA = [&](int st, float4 v0, float4 v1){
    float xv[8] = {v0.x,v0.y,v0.z,v0.w,v1.x,v1.y,v1.z,v1.w};
    union { __half b[8]; uint4 u; } hi;
    #pragma unroll
    for(int e=0;e<8;e++) hi.b[e] = __float2half_rn(xv[e]);
    int sub = aq >> 1;
    *reinterpret_cast<uint4*>(sm + K4_SA(st,sub) + arow*48 + (aq&1)*16) = hi.u;
  };

  /* prolog: stages 0 and 1 */
  {
    float4 v0 = *reinterpret_cast<const float4*>(aptr);
    float4 v1 = *reinterpret_cast<const float4*>(aptr + 4);
    cvtstA(0, v0, v1);
    loadB(0, 0); CPCOMMIT();
    v0 = *reinterpret_cast<const float4*>(aptr + 32);
    v1 = *reinterpret_cast<const float4*>(aptr + 36);
    cvtstA(1, v0, v1);
    loadB(1, 1); CPCOMMIT();
  }

  const uint32 a_off = (uint32)((wm*32 + (lane&15))*48 + (lane>>4)*16);
  const int bnl = (lane&7) + ((lane>>4)&1)*8;
  const uint32 b_off = (uint32)((wn*64 + bnl)*32
                     + ((((lane>>3)&1) ^ ((bnl>>2)&1)) << 4));

  float acc[2][8][4];
  #pragma unroll
  for(int mt=0;mt<2;mt++)
    #pragma unroll
    for(int nt=0;nt<8;nt++)
      #pragma unroll
      for(int c=0;c<4;c++) acc[mt][nt][c] = 0.f;

  for(int kc=0; kc<16; kc++){                 /* 16 chunks of k=32 */
    const int st = kc % 3;
    float4 pv0, pv1;
    const bool more = (kc+2 < 16);
    if(more){                                 /* issue A LDG early (latency) */
      pv0 = *reinterpret_cast<const float4*>(aptr + (kc+2)*32);
      pv1 = *reinterpret_cast<const float4*>(aptr + (kc+2)*32 + 4);
    }
    if(kc < 15) CPWAIT(1); else CPWAIT(0);    /* FIX: complete chunk kc */
    __syncthreads();

    #pragma unroll
    for(int sub=0; sub<2; sub++){
      uint32 af[2][4], bf[4][4];
      const uint32 ahi = sb + K4_SA(st,sub) + a_off;
      const uint32 bba = sb + K4_SB(st,sub) + b_off;

      LDSM4(af[0], ahi);
      LDSM4(af[1], ahi + 16*48);
      #pragma unroll
      for(int x=0;x<4;x++) LDSM4(bf[x], bba + x*512);

      #pragma unroll
      for(int mt=0;mt<2;mt++)
        #pragma unroll
        for(int x=0;x<4;x++){
          MMA16816(acc[mt][2*x],   af[mt], bf[x][0], bf[x][1]);
          MMA16816(acc[mt][2*x+1], af[mt], bf[x][2], bf[x][3]);
        }
    }
    if(more){
      int st2 = (kc+2) % 3;
      loadB(kc+2, st2); CPCOMMIT();
      cvtstA(st2, pv0, pv1);
    }
  }

  /* ---- epilogue: +y, relu, partial dot over this CTA's 256 cols ---- */
  __syncthreads();
  const int r = lane >> 2, q = lane & 3;
  float rsum[4] = {0.f,0.f,0.f,0.f};
  #pragma unroll
  for(int mt=0;mt<2;mt++){
    int row0 = wm*32 + mt*16 + r;
    int row1 = row0 + 8;
    int bs0 = (int)((m0 + row0) / NSMP);
    int bs1 = (int)((m0 + row1) / NSMP);
    const float* y0 = g_y + (size_t)bs0*HH + n0 + wn*64;
    const float* y1 = g_y + (size_t)bs1*HH + n0 + wn*64;
    const float* wtp = wtime + n0 + wn*64;
    #pragma unroll
    for(int nt=0;nt<8;nt++){
      int col = nt*8 + q*2;
      float w0 = wtp[col], w1 = wtp[col+1];
      float* c = acc[mt][nt];
      rsum[mt*2+0] += fmaxf(c[0]+y0[col],0.f)*w0 + fmaxf(c[1]+y0[col+1],0.f)*w1;
      rsum[mt*2+1] += fmaxf(c[2]+y1[col],0.f)*w0 + fmaxf(c[3]+y1[col+1],0.f)*w1;
    }
  }
  float* rs = reinterpret_cast<float*>(sm);   /* reuse stage0: [128][4] */
  #pragma unroll
  for(int s=0;s<4;s++){
    float v = rsum[s];
    v += __shfl_xor_sync(0xffffffffu, v, 1);
    v += __shfl_xor_sync(0xffffffffu, v, 2);
    if(q==0){
      int row = wm*32 + (s>>1)*16 + (s&1)*8 + r;
      rs[row*4 + wn] = v;
    }
  }
  __syncthreads();
  if(t < 128){
    g_part[(size_t)blockIdx.y*RTOT + m0 + t] =
      rs[t*4] + rs[t*4+1] + rs[t*4+2] + rs[t*4+3];
  }
}

/* -------- k5: combine N-halves, softplus, mean over NS -> pred ------------- */
__global__ void k5_pred(float* __restrict__ pred){
  int bs = blockIdx.x, lane = threadIdx.x;    /* 32 threads */
  float s = 0.f;
  for(int i=lane; i<NSMP; i+=32){
    size_t idx = (size_t)bs*NSMP + i;
    s += softplusf(g_part[idx] + g_part[RTOT + idx]);
  }
  #pragma unroll
  for(int o=16;o;o>>=1) s += __shfl_xor_sync(0xffffffffu, s, o);
  if(lane==0) pred[bs] = s * (1.f/NSMP);
}

/* ---------------- launch ---------------- */
extern "C" void kernel_launch(void* const* d_in, const int* in_sizes, int n_in,
                              void* d_out, int out_size){
  const int*   etype  = (const int*)  d_in[0];
  const float* etime  = (const float*)d_in[1];
  const float* noise  = (const float*)d_in[2];
  const float* wt     = (const float*)d_in[3];
  const float* table  = (const float*)d_in[4];
  const float* wsig   = (const float*)d_in[5];
  const float* wgate  = (const float*)d_in[6];
  const float* gamma  = (const float*)d_in[7];
  const float* beta   = (const float*)d_in[8];
  const float* wpred  = (const float*)d_in[9];
  const float* w_in   = (const float*)d_in[10];
  const float* wnoise = (const float*)d_in[11];
  const float* wtime  = (const float*)d_in[12];
  float* out = (float*)d_out;

  cudaFuncSetAttribute(k4_mma, cudaFuncAttributeMaxDynamicSharedMemorySize, K4_SMEM);
  cudaFuncSetAttribute(k3y_mma, cudaFuncAttributeMaxDynamicSharedMemorySize, Y_SMEM);
  cudaFuncSetAttribute(k2_agg, cudaFuncAttributeMaxDynamicSharedMemorySize, K2_SMEM);

  k1_pre<<<MM, 256>>>(etype, etime, wt, table, wsig, wgate, wnoise, w_in);
  k2_agg<<<BB*(SS/32), 256, K2_SMEM>>>(etime);
  k3_ln <<<MM, 256>>>(gamma, beta, wpred, out + MM);
  k3y_mma<<<dim3(MM/64, 2), 256, Y_SMEM>>>();
  k4_mma<<<dim3(RTOT/128, 2), 512, K4_SMEM>>>(noise, wtime);
  k5_pred<<<MM, 32>>>(out);
}

// round 16
// speedup vs baseline: 1.2157x; 1.2157x over previous
#include <cuda_runtime.h>
#include <cuda_fp16.h>
#include <math.h>
#include <stdint.h>

#define BB 4
#define SS 1024
#define DD 256
#define HH 512
#define NTY 20
#define NSMP 50
#define MM (BB*SS)          /* 4096 (b,s) rows */
#define RTOT (MM*NSMP)      /* 204800 GEMM rows */

typedef unsigned long long ull;
typedef unsigned int uint32;

/* ---------------- scratch (device globals; no allocs allowed) -------------- */
__device__ __align__(16) float g_hvec[MM*HH];   /* [b,s, pe|temb]   8MB */
__device__ __align__(16) float g_hid [MM*HH];   /* aggregated (j-half 0) 8MB */
__device__ __align__(16) float g_hid2[MM*HH];   /* aggregated (j-half 1) 8MB */
__device__ __align__(16) float g_y   [MM*HH];   /* hln @ w_in^T     8MB */
/* fp16 weights, k-chunk-major: elem (n,k) at (k/16)*8192 + n*16 + (k%16) */
__device__ __align__(16) __half g_wh [HH*HH];   /* w_noise fp16 */
__device__ __align__(16) __half g_wih[HH*HH];   /* w_in hi */
__device__ __align__(16) __half g_wil[HH*HH];   /* w_in lo */
__device__ __align__(16) float g_part[2*RTOT];  /* partial relu-dots 1.6MB */
__device__ float g_asv[MM], g_bsv[MM], g_agv[MM], g_bgv[MM];

/* ---------------- small helpers ---------------- */
__device__ __forceinline__ ull ffma2(ull a, ull b, ull c){
  ull d; asm("fma.rn.f32x2 %0, %1, %2, %3;" : "=l"(d) : "l"(a), "l"(b), "l"(c)); return d;
}
union F2 { ull u; float2 f; };
__device__ __forceinline__ ull pack2(float x, float y){ F2 t; t.f = make_float2(x,y); return t.u; }

__device__ __forceinline__ float block_sum256(float v){
  __shared__ float sh[8];
  int lane = threadIdx.x & 31, w = threadIdx.x >> 5;
  #pragma unroll
  for(int o=16;o;o>>=1) v += __shfl_xor_sync(0xffffffffu, v, o);
  if(lane==0) sh[w] = v;
  __syncthreads();
  if(w==0){
    float r = (lane<8)?sh[lane]:0.f;
    #pragma unroll
    for(int o=4;o;o>>=1) r += __shfl_xor_sync(0xffffffffu, r, o);
    if(lane==0) sh[0]=r;
  }
  __syncthreads();
  float r = sh[0];
  __syncthreads();
  return r;
}

__device__ __forceinline__ float softplusf(float x){
  return fmaxf(x,0.f) + log1pf(expf(-fabsf(x)));
}

__device__ __forceinline__ uint32 smem_u32(const void* p){
  uint32 a; asm("{ .reg .u64 t; cvta.to.shared.u64 t, %1; cvt.u32.u64 %0, t; }" : "=r"(a) : "l"(p));
  return a;
}

/* ---------------- sm80-class tensor core primitives (portable) ------------- */
#define LDSM4(rg, addr) \
  asm volatile("ldmatrix.sync.aligned.m8n8.x4.shared.b16 {%0,%1,%2,%3}, [%4];" \
    : "=r"((rg)[0]),"=r"((rg)[1]),"=r"((rg)[2]),"=r"((rg)[3]) : "r"(addr))

#define MMA16816(cd, a, b0, b1) \
  asm volatile("mma.sync.aligned.m16n8k16.row.col.f32.f16.f16.f32 " \
    "{%0,%1,%2,%3},{%4,%5,%6,%7},{%8,%9},{%0,%1,%2,%3};" \
    : "+f"((cd)[0]),"+f"((cd)[1]),"+f"((cd)[2]),"+f"((cd)[3]) \
    : "r"((a)[0]),"r"((a)[1]),"r"((a)[2]),"r"((a)[3]), "r"(b0),"r"(b1))

#define CPA16(s,g)  asm volatile("cp.async.cg.shared.global [%0], [%1], 16;" :: "r"(s), "l"(g))
#define CPCOMMIT()  asm volatile("cp.async.commit_group;" ::: "memory")
#define CPWAIT(n)   asm volatile("cp.async.wait_group %0;" :: "n"(n) : "memory")

/* -------- k0: w_noise -> fp16; w_in -> fp16 hi/lo; k-chunk-major ----------- */
__global__ void k0_conv(const float* __restrict__ wn, const float* __restrict__ wi){
  int g = blockIdx.x*256 + threadIdx.x;       /* 32768 threads, 8 elems each */
  int n = g >> 6; int k = (g & 63) * 8;
  int dst = (k>>4)*8192 + n*16 + (k&15);
  {
    const float4* s = reinterpret_cast<const float4*>(wn + (size_t)n*HH + k);
    float4 v0 = s[0], v1 = s[1];
    float xs[8] = {v0.x,v0.y,v0.z,v0.w,v1.x,v1.y,v1.z,v1.w};
    union { __half b[8]; uint4 u; } h;
    #pragma unroll
    for(int e=0;e<8;e++) h.b[e] = __float2half_rn(xs[e]);
    *reinterpret_cast<uint4*>(g_wh + dst) = h.u;
  }
  {
    const float4* s = reinterpret_cast<const float4*>(wi + (size_t)n*HH + k);
    float4 v0 = s[0], v1 = s[1];
    float xs[8] = {v0.x,v0.y,v0.z,v0.w,v1.x,v1.y,v1.z,v1.w};
    union { __half b[8]; uint4 u; } hi, lo;
    #pragma unroll
    for(int e=0;e<8;e++){
      __half h = __float2half_rn(xs[e]);
      hi.b[e] = h;
      lo.b[e] = __float2half_rn(xs[e] - __half2float(h));
    }
    *reinterpret_cast<uint4*>(g_wih + dst) = hi.u;
    *reinterpret_cast<uint4*>(g_wil + dst) = lo.u;
  }
}

/* -------- k1: pe + type emb + per-event sigma/gate projections ------------- */
__global__ void k1_pre(const int* __restrict__ etype, const float* __restrict__ etime,
                       const float* __restrict__ wt, const float* __restrict__ table,
                       const float* __restrict__ wsig, const float* __restrict__ wgate){
  int bs = blockIdx.x; int t = threadIdx.x;
  int s = bs & (SS-1);
  float tv = table[(size_t)etype[bs]*DD + t];
  float tm = etime[bs];
  if(t < DD/2){
    double div = exp(-(double)(2*t) * (9.210340371976184/256.0)); /* ln(1e4)/d */
    float arg = (float)((double)s * div) + tm * wt[t];
    g_hvec[(size_t)bs*HH + t]        = sinf(arg);
    g_hvec[(size_t)bs*HH + DD/2 + t] = cosf(arg);
  }
  g_hvec[(size_t)bs*HH + DD + t] = tv;
  float r;
  r = block_sum256(tv * wsig[t]);      if(t==0) g_asv[bs]=r;
  r = block_sum256(tv * wsig[DD+t]);   if(t==0) g_bsv[bs]=r;
  r = block_sum256(tv * wgate[t]);     if(t==0) g_agv[bs]=r;
  r = block_sum256(tv * wgate[DD+t]);  if(t==0) g_bgv[bs]=r;
}

/* -------- k2: causal gated score aggregation, TI=32 rows per block,
   j-range SPLIT across 2 CTAs by 256-tile parity (load balance + all SMs).
   half 0 -> g_hid, half 1 -> g_hid2; k3_ln sums them.                      */
#define K2_SMEM (32*256*8)
__global__ void __launch_bounds__(256) k2_agg(const float* __restrict__ etime){
  extern __shared__ ull s_w[];                 /* [32][256] = 64KB */
  __shared__ float s_bs[32], s_bg[32], s_ti[32];
  int bx = blockIdx.x;
  int half = bx & 1; int rest = bx >> 1;
  int b = rest >> 5;
  int i0 = (31 - (rest & 31)) << 5;           /* reversed: big tiles first */
  int t = threadIdx.x;
  if(t < 32){
    int i = b*SS + i0 + t;
    s_bs[t] = g_bsv[i]; s_bg[t] = g_bgv[i]; s_ti[t] = etime[i];
  }
  __syncthreads();
  ull acc[32];
  #pragma unroll
  for(int r=0;r<32;r++) acc[r]=0ull;
  int jend = i0 + 31;                /* max needed j is i0+30 (strict causal) */
  for(int j0 = half*256; j0 < jend; j0 += 512){
    int j = j0 + t;
    float aj_s = g_asv[b*SS+j], aj_g = g_agv[b*SS+j], tj = etime[b*SS+j];
    #pragma unroll
    for(int r=0;r<32;r++){
      float sig  = __logf(1.f + __expf(aj_s + s_bs[r]));
      float gate = 1.f/(1.f + __expf(-(aj_g + s_bg[r])));
      float td   = fabsf(s_ti[r]-tj);
      float wv   = (j < i0+r) ? gate*__expf(-sig*td) : 0.f;
      s_w[r*256 + t] = pack2(wv, wv);
    }
    __syncthreads();
    int jcnt = min(256, jend - j0);
    const ull* hv = reinterpret_cast<const ull*>(g_hvec) + ((size_t)(b*SS + j0))*256 + t;
    #pragma unroll 2
    for(int jj=0;jj<jcnt;jj++){
      ull v = hv[(size_t)jj*256];
      #pragma unroll
      for(int r=0;r<32;r++) acc[r] = ffma2(s_w[r*256 + jj], v, acc[r]);
    }
    __syncthreads();
  }
  float* dst = half ? g_hid2 : g_hid;
  #pragma unroll
  for(int r=0;r<32;r++)
    reinterpret_cast<ull*>(dst)[((size_t)(b*SS + i0 + r))*256 + t] = acc[r];
}

/* -------- k3: LayerNorm (sums the two j-halves) + mark_probs softmax ------- */
__global__ void k3_ln(const float* __restrict__ gamma, const float* __restrict__ beta,
                      const float* __restrict__ wpred, float* __restrict__ marks){
  __shared__ float s_n[HH];
  __shared__ float slog[NTY];
  int bs = blockIdx.x, t = threadIdx.x;
  float2 h0 = reinterpret_cast<const float2*>(g_hid )[(size_t)bs*256 + t];
  float2 h1 = reinterpret_cast<const float2*>(g_hid2)[(size_t)bs*256 + t];
  float2 h = make_float2(h0.x + h1.x, h0.y + h1.y);
  float mean = block_sum256(h.x + h.y) * (1.f/HH);
  float dx = h.x - mean, dy = h.y - mean;
  float var = block_sum256(dx*dx + dy*dy) * (1.f/HH);
  float inv = rsqrtf(var + 1e-6f);
  float n0 = dx*inv*gamma[2*t]   + beta[2*t];
  float n1 = dy*inv*gamma[2*t+1] + beta[2*t+1];
  reinterpret_cast<float2*>(g_hid)[(size_t)bs*256 + t] = make_float2(n0,n1);
  s_n[2*t]=n0; s_n[2*t+1]=n1;
  __syncthreads();
  int lane = t & 31, w = t >> 5;
  for(int nt = w; nt < NTY; nt += 8){
    float p = 0.f;
    for(int k=lane;k<HH;k+=32) p += s_n[k]*wpred[(size_t)nt*HH+k];
    #pragma unroll
    for(int o=16;o;o>>=1) p += __shfl_xor_sync(0xffffffffu,p,o);
    if(lane==0) slog[nt]=p;
  }
  __syncthreads();
  if(t==0){
    float mx=-1e30f;
    for(int c=0;c<NTY;c++) mx = fmaxf(mx, slog[c]);
    float e[NTY], sum=0.f;
    for(int c=0;c<NTY;c++){ e[c]=expf(slog[c]-mx); sum+=e[c]; }
    float is = 1.f/sum;
    for(int c=0;c<NTY;c++) marks[(size_t)bs*NTY + c] = e[c]*is;
  }
}

/* -------- k3y: y = hln @ w_in^T on tensor cores, 3-pass split-fp16 --------- */
#define Y_SAH(buf) ((buf)*3072)                 /* 64 rows x 48B pitch */
#define Y_SAL(buf) (6144 + (buf)*3072)
#define Y_SBH(buf) (12288 + (buf)*8192)         /* 256 n x 32B */
#define Y_SBL(buf) (28672 + (buf)*8192)
#define Y_SMEM 45056

__global__ void __launch_bounds__(256,1)
k3y_mma(){
  extern __shared__ char sm[];
  const uint32 sb = smem_u32(sm);
  const int t = threadIdx.x;
  const int lane = t & 31, w = t >> 5;
  const int wm = w & 1, wn = w >> 1;          /* 2 M-warps x 4 N-warps */
  const size_t m0 = (size_t)blockIdx.x * 64;
  const int n0 = blockIdx.y * 256;

  const int arow = t >> 1, ahalf = t & 1;     /* t<128 active for A */
  const float* aptr = g_hid + (m0 + arow)*HH + ahalf*8;

  auto loadB = [&](int kc, int buf){
    const char* srch = reinterpret_cast<const char*>(g_wih) + (size_t)kc*16384;
    const char* srcl = reinterpret_cast<const char*>(g_wil) + (size_t)kc*16384;
    #pragma unroll
    for(int j=0;j<2;j++){
      int i = t + j*256;
      int n = i >> 1, kq = i & 1;
      int soff = n*32 + ((kq ^ ((n>>2)&1)) << 4);
      int goff = (n0 + n)*32 + (kq << 4);
      CPA16(sb + Y_SBH(buf) + soff, srch + goff);
      CPA16(sb + Y_SBL(buf) + soff, srcl + goff);
    }
  };
  auto cvtstA = [&](int buf, float4 v0, float4 v1){
    if(t < 128){
      float xv[8] = {v0.x,v0.y,v0.z,v0.w,v1.x,v1.y,v1.z,v1.w};
      union { __half b[8]; uint4 u; } hi, lo;
      #pragma unroll
      for(int e=0;e<8;e++){
        __half h = __float2half_rn(xv[e]);
        hi.b[e] = h;
        lo.b[e] = __float2half_rn(xv[e] - __half2float(h));
      }
      int off = arow*48 + ahalf*16;
      *reinterpret_cast<uint4*>(sm + Y_SAH(buf) + off) = hi.u;
      *reinterpret_cast<uint4*>(sm + Y_SAL(buf) + off) = lo.u;
    }
  };

  float4 pv0, pv1;
  if(t < 128){ pv0 = *reinterpret_cast<const float4*>(aptr);
               pv1 = *reinterpret_cast<const float4*>(aptr + 4); }
  cvtstA(0, pv0, pv1);
  loadB(0, 0); CPCOMMIT();

  const uint32 a_off = (uint32)((wm*32 + (lane&15))*48 + (lane>>4)*16);
  const int bnl = (lane&7) + ((lane>>4)&1)*8;
  const uint32 b_off = (uint32)((wn*64 + bnl)*32
                     + ((((lane>>3)&1) ^ ((bnl>>2)&1)) << 4));

  float acc[2][8][4];
  #pragma unroll
  for(int mt=0;mt<2;mt++)
    #pragma unroll
    for(int nt=0;nt<8;nt++)
      #pragma unroll
      for(int c=0;c<4;c++) acc[mt][nt][c] = 0.f;

  for(int kc=0; kc<32; kc++){
    const int buf = kc & 1;
    if(kc < 31){
      if(t < 128){ pv0 = *reinterpret_cast<const float4*>(aptr + (kc+1)*16);
                   pv1 = *reinterpret_cast<const float4*>(aptr + (kc+1)*16 + 4); }
      loadB(kc+1, buf^1); CPCOMMIT();
      CPWAIT(1);
    } else CPWAIT(0);
    __syncthreads();

    uint32 af[2][4], al[2][4], bh[4][4], bl[4][4];
    const uint32 ahi = sb + Y_SAH(buf) + a_off;
    const uint32 alo = sb + Y_SAL(buf) + a_off;
    const uint32 bhb = sb + Y_SBH(buf) + b_off;
    const uint32 blb = sb + Y_SBL(buf) + b_off;

    LDSM4(af[0], ahi);  LDSM4(af[1], ahi + 16*48);
    LDSM4(al[0], alo);  LDSM4(al[1], alo + 16*48);
    #pragma unroll
    for(int x=0;x<4;x++){ LDSM4(bh[x], bhb + x*512); LDSM4(bl[x], blb + x*512); }

    #pragma unroll
    for(int mt=0;mt<2;mt++)
      #pragma unroll
      for(int x=0;x<4;x++){
        MMA16816(acc[mt][2*x],   af[mt], bh[x][0], bh[x][1]);
        MMA16816(acc[mt][2*x+1], af[mt], bh[x][2], bh[x][3]);
        MMA16816(acc[mt][2*x],   al[mt], bh[x][0], bh[x][1]);
        MMA16816(acc[mt][2*x+1], al[mt], bh[x][2], bh[x][3]);
        MMA16816(acc[mt][2*x],   af[mt], bl[x][0], bl[x][1]);
        MMA16816(acc[mt][2*x+1], af[mt], bl[x][2], bl[x][3]);
      }
    if(kc < 31) cvtstA(buf^1, pv0, pv1);
    __syncthreads();
  }

  /* write y (fp32) */
  const int r = lane >> 2, q = lane & 3;
  #pragma unroll
  for(int mt=0;mt<2;mt++){
    size_t row0 = m0 + wm*32 + mt*16 + r;
    size_t row1 = row0 + 8;
    #pragma unroll
    for(int nt=0;nt<8;nt++){
      int col = n0 + wn*64 + nt*8 + q*2;
      float* c = acc[mt][nt];
      *reinterpret_cast<float2*>(&g_y[row0*HH + col]) = make_float2(c[0],c[1]);
      *reinterpret_cast<float2*>(&g_y[row1*HH + col]) = make_float2(c[2],c[3]);
    }
  }
}

/* -------- k4: single-pass fp16 mma.sync GEMM, M=128 x N=256 per CTA --------
   512 threads / 16 warps (4 per SMSP); warp tile 32x64; K-chunk 32 with two
   16-k sub-steps; 2-stage double buffer (R11 proven config).               */
#define SA(buf,sub) ((buf)*12288 + (sub)*6144)  /* 128 rows x 48B pitch */
#define SB(buf,sub) (24576 + (buf)*16384 + (sub)*8192)  /* 256 n x 32B */
#define K4_SMEM 57344

__global__ void __launch_bounds__(512,1)
k4_mma(const float* __restrict__ noise, const float* __restrict__ wtime){
  extern __shared__ char sm[];
  const uint32 sb = smem_u32(sm);
  const int t = threadIdx.x;
  const int lane = t & 31, w = t >> 5;
  const int wm = w & 3, wn = w >> 2;          /* 4 M-warps x 4 N-warps */
  const size_t m0 = (size_t)blockIdx.x * 128;
  const int n0 = blockIdx.y * 256;

  const int arow = t >> 2, aq = t & 3;        /* 4 threads/row, 8 floats each */
  const float* aptr = noise + (m0 + arow)*HH + aq*8;

  auto loadB = [&](int kc2, int buf){         /* kc2: 32-wide chunk index */
    #pragma unroll
    for(int sub=0; sub<2; sub++){
      const char* src = reinterpret_cast<const char*>(g_wh)
                      + (size_t)(kc2*2+sub)*16384;
      int n = t >> 1, kq = t & 1;             /* 512 lines of 16B */
      int soff = n*32 + ((kq ^ ((n>>2)&1)) << 4);
      int goff = (n0 + n)*32 + (kq << 4);
      CPA16(sb + SB(buf,sub) + soff, src + goff);
    }
  };
  auto cvtstA = [&](int buf, float4 v0, float4 v1){
    float xv[8] = {v0.x,v0.y,v0.z,v0.w,v1.x,v1.y,v1.z,v1.w};
    union { __half b[8]; uint4 u; } hi;
    #pragma unroll
    for(int e=0;e<8;e++) hi.b[e] = __float2half_rn(xv[e]);
    int sub = aq >> 1;
    *reinterpret_cast<uint4*>(sm + SA(buf,sub) + arow*48 + (aq&1)*16) = hi.u;
  };

  float4 pv0 = *reinterpret_cast<const float4*>(aptr);
  float4 pv1 = *reinterpret_cast<const float4*>(aptr + 4);
  cvtstA(0, pv0, pv1);
  loadB(0, 0); CPCOMMIT();

  const uint32 a_off = (uint32)((wm*32 + (lane&15))*48 + (lane>>4)*16);
  const int bnl = (lane&7) + ((lane>>4)&1)*8;
  const uint32 b_off = (uint32)((wn*64 + bnl)*32
                     + ((((lane>>3)&1) ^ ((bnl>>2)&1)) << 4));

  float acc[2][8][4];
  #pragma unroll
  for(int mt=0;mt<2;mt++)
    #pragma unroll
    for(int nt=0;nt<8;nt++)
      #pragma unroll
      for(int c=0;c<4;c++) acc[mt][nt][c] = 0.f;

  for(int kc=0; kc<16; kc++){                 /* 16 chunks of k=32 */
    const int buf = kc & 1;
    if(kc < 15){
      pv0 = *reinterpret_cast<const float4*>(aptr + (kc+1)*32);
      pv1 = *reinterpret_cast<const float4*>(aptr + (kc+1)*32 + 4);
      loadB(kc+1, buf^1); CPCOMMIT();
      CPWAIT(1);
    } else CPWAIT(0);
    __syncthreads();

    #pragma unroll
    for(int sub=0; sub<2; sub++){
      uint32 af[2][4], bf[4][4];
      const uint32 ahi = sb + SA(buf,sub) + a_off;
      const uint32 bba = sb + SB(buf,sub) + b_off;

      LDSM4(af[0], ahi);
      LDSM4(af[1], ahi + 16*48);
      #pragma unroll
      for(int x=0;x<4;x++) LDSM4(bf[x], bba + x*512);

      #pragma unroll
      for(int mt=0;mt<2;mt++)
        #pragma unroll
        for(int x=0;x<4;x++){
          MMA16816(acc[mt][2*x],   af[mt], bf[x][0], bf[x][1]);
          MMA16816(acc[mt][2*x+1], af[mt], bf[x][2], bf[x][3]);
        }
    }
    if(kc < 15) cvtstA(buf^1, pv0, pv1);
    __syncthreads();
  }

  /* ---- epilogue: +y, relu, partial dot over this CTA's 256 cols ---- */
  const int r = lane >> 2, q = lane & 3;
  float rsum[4] = {0.f,0.f,0.f,0.f};
  #pragma unroll
  for(int mt=0;mt<2;mt++){
    int row0 = wm*32 + mt*16 + r;
    int row1 = row0 + 8;
    int bs0 = (int)((m0 + row0) / NSMP);
    int bs1 = (int)((m0 + row1) / NSMP);
    const float* y0 = g_y + (size_t)bs0*HH + n0 + wn*64;
    const float* y1 = g_y + (size_t)bs1*HH + n0 + wn*64;
    const float* wtp = wtime + n0 + wn*64;
    #pragma unroll
    for(int nt=0;nt<8;nt++){
      int col = nt*8 + q*2;
      float w0 = wtp[col], w1 = wtp[col+1];
      float* c = acc[mt][nt];
      rsum[mt*2+0] += fmaxf(c[0]+y0[col],0.f)*w0 + fmaxf(c[1]+y0[col+1],0.f)*w1;
      rsum[mt*2+1] += fmaxf(c[2]+y1[col],0.f)*w0 + fmaxf(c[3]+y1[col+1],0.f)*w1;
    }
  }
  float* rs = reinterpret_cast<float*>(sm);   /* reuse A region: [128][4] */
  #pragma unroll
  for(int s=0;s<4;s++){
    float v = rsum[s];
    v += __shfl_xor_sync(0xffffffffu, v, 1);
    v += __shfl_xor_sync(0xffffffffu, v, 2);
    if(q==0){
      int row = wm*32 + (s>>1)*16 + (s&1)*8 + r;
      rs[row*4 + wn] = v;
    }
  }
  __syncthreads();
  if(t < 128){
    g_part[(size_t)blockIdx.y*RTOT + m0 + t] =
      rs[t*4] + rs[t*4+1] + rs[t*4+2] + rs[t*4+3];
  }
}

/* -------- k5: combine N-halves, softplus, mean over NS -> pred ------------- */
__global__ void k5_pred(float* __restrict__ pred){
  int bs = blockIdx.x, lane = threadIdx.x;    /* 32 threads */
  float s = 0.f;
  for(int i=lane; i<NSMP; i+=32){
    size_t idx = (size_t)bs*NSMP + i;
    s += softplusf(g_part[idx] + g_part[RTOT + idx]);
  }
  #pragma unroll
  for(int o=16;o;o>>=1) s += __shfl_xor_sync(0xffffffffu, s, o);
  if(lane==0) pred[bs] = s * (1.f/NSMP);
}

/* ---------------- launch ---------------- */
extern "C" void kernel_launch(void* const* d_in, const int* in_sizes, int n_in,
                              void* d_out, int out_size){
  const int*   etype  = (const int*)  d_in[0];
  const float* etime  = (const float*)d_in[1];
  const float* noise  = (const float*)d_in[2];
  const float* wt     = (const float*)d_in[3];
  const float* table  = (const float*)d_in[4];
  const float* wsig   = (const float*)d_in[5];
  const float* wgate  = (const float*)d_in[6];
  const float* gamma  = (const float*)d_in[7];
  const float* beta   = (const float*)d_in[8];
  const float* wpred  = (const float*)d_in[9];
  const float* w_in   = (const float*)d_in[10];
  const float* wnoise = (const float*)d_in[11];
  const float* wtime  = (const float*)d_in[12];
  float* out = (float*)d_out;

  cudaFuncSetAttribute(k4_mma, cudaFuncAttributeMaxDynamicSharedMemorySize, K4_SMEM);
  cudaFuncSetAttribute(k3y_mma, cudaFuncAttributeMaxDynamicSharedMemorySize, Y_SMEM);
  cudaFuncSetAttribute(k2_agg, cudaFuncAttributeMaxDynamicSharedMemorySize, K2_SMEM);

  k0_conv<<<HH*HH/(256*8), 256>>>(wnoise, w_in);
  k1_pre<<<MM, 256>>>(etype, etime, wt, table, wsig, wgate);
  k2_agg<<<BB*(SS/32)*2, 256, K2_SMEM>>>(etime);
  k3_ln <<<MM, 256>>>(gamma, beta, wpred, out + MM);
  k3y_mma<<<dim3(MM/64, 2), 256, Y_SMEM>>>();
  k4_mma<<<dim3(RTOT/128, 2), 512, K4_SMEM>>>(noise, wtime);
  k5_pred<<<MM, 32>>>(out);
}